// round 15
// baseline (speedup 1.0000x reference)
#include <cuda_runtime.h>
#include <cuda_fp16.h>
#include <math.h>

#define NN 50000
#define DD 64
#define EE 1250000
#define BB 4096
#define ROW4 16              // float4 per embedding row
#define EPAD (EE + 3 * NN)   // CSR rows padded to multiple of 4 edges

// ---------------- scratch (device globals; no allocation) ----------------
__device__ float g_embA[NN * DD];
__device__ float g_embB[NN * DD];
__device__ float g_agg [NN * DD];
__device__ __align__(256) __half2 g_embH[NN * DD / 2];   // fp16 mirror, 128B rows
__device__ float g_ue[BB * 256];
__device__ float g_pe[BB * 256];
__device__ float g_ne[BB * 256];
// CSR build scratch
__device__ int       g_cnt[NN];
__device__ int       g_rowstart[NN + 1];
__device__ int       g_cursor[NN];
__device__ long long g_pedge[EPAD];     // packed: low32=col, high32=val bits

// ---------------- tf32 helpers ----------------
__device__ __forceinline__ unsigned f2tf(float f) {
    unsigned r;
    asm("cvt.rna.tf32.f32 %0, %1;" : "=r"(r) : "f"(f));
    return r;
}
__device__ __forceinline__ void tfsplit(float f, unsigned& hi, unsigned& lo) {
    hi = f2tf(f);
    float r = f - __uint_as_float(hi);
    lo = f2tf(r);
}
__device__ __forceinline__ void mma_tf32(float* d, const unsigned* a,
                                         unsigned b0, unsigned b1) {
    asm volatile(
        "mma.sync.aligned.m16n8k8.row.col.f32.tf32.tf32.f32 "
        "{%0,%1,%2,%3},{%4,%5,%6,%7},{%8,%9},{%0,%1,%2,%3};"
        : "+f"(d[0]), "+f"(d[1]), "+f"(d[2]), "+f"(d[3])
        : "r"(a[0]), "r"(a[1]), "r"(a[2]), "r"(a[3]), "r"(b0), "r"(b1));
}

// ---------------- CSR build ----------------

__global__ void zero_cnt_kernel() {
    int i = blockIdx.x * blockDim.x + threadIdx.x;
    if (i < NN) g_cnt[i] = 0;
}

__global__ void hist_kernel(const int* __restrict__ rows) {
    int e = blockIdx.x * blockDim.x + threadIdx.x;
    if (e < EE) atomicAdd(&g_cnt[rows[e]], 1);
}

#define SCAN_T 1024
#define SCAN_CH 49           // 49*1024 = 50176 >= NN
__global__ void scan_kernel() {
    __shared__ int part[SCAN_T];
    const int t = threadIdx.x;
    const int base = t * SCAN_CH;
    int s = 0;
#pragma unroll
    for (int i = 0; i < SCAN_CH; i++) {
        int idx = base + i;
        if (idx < NN) s += (g_cnt[idx] + 3) & ~3;
    }
    part[t] = s;
    __syncthreads();
    for (int d = 1; d < SCAN_T; d <<= 1) {
        int v = 0;
        if (t >= d) v = part[t - d];
        __syncthreads();
        if (t >= d) part[t] += v;
        __syncthreads();
    }
    int run = part[t] - s;
    for (int i = 0; i < SCAN_CH; i++) {
        int idx = base + i;
        if (idx < NN) {
            g_rowstart[idx] = run;
            g_cursor[idx]   = run;
            run += (g_cnt[idx] + 3) & ~3;
        }
    }
    if (t == SCAN_T - 1) g_rowstart[NN] = part[SCAN_T - 1];
}

// Zero the <=3 pad slots per row (col=0, val=0.0 is a no-op edge).
__global__ void pad_zero_kernel() {
    int r = blockIdx.x * blockDim.x + threadIdx.x;
    if (r >= NN) return;
    int p = g_rowstart[r] + g_cnt[r];
    int e = g_rowstart[r + 1];
    for (; p < e; p++) g_pedge[p] = 0LL;
}

__global__ void scatter_kernel(const int*  __restrict__ rows,
                               const int*  __restrict__ cols,
                               const float* __restrict__ vals) {
    int e = blockIdx.x * blockDim.x + threadIdx.x;
    if (e >= EE) return;
    int r = rows[e];
    int p = atomicAdd(&g_cursor[r], 1);
    long long packed = ((long long)__float_as_int(vals[e]) << 32) |
                       (unsigned)cols[e];
    g_pedge[p] = packed;
}

// ---------------- fp16 mirror of the initial embedding ----------------
__global__ void conv_half_kernel(const float* __restrict__ src) {
    int i = blockIdx.x * blockDim.x + threadIdx.x;   // half2 index
    if (i >= NN * DD / 2) return;
    float2 v = reinterpret_cast<const float2*>(src)[i];
    g_embH[i] = __floats2half2_rn(v.x, v.y);
}

// ---------------- SpMM (CSR, shfl-broadcast, fp16 gather) ----------------
// One warp per row; lane l owns half2 chunk l (2 elems) -> 128B/row = 1 line.
__global__ void __launch_bounds__(256) spmm_csr_kernel() {
    const int w = blockIdx.x * 8 + (threadIdx.x >> 5);
    if (w >= NN) return;
    const int lane = threadIdx.x & 31;
    const int s = g_rowstart[w];
    const int e = g_rowstart[w + 1];

    float2 a0 = make_float2(0.f, 0.f);
    float2 a1 = make_float2(0.f, 0.f);
    float2 a2 = make_float2(0.f, 0.f);
    float2 a3 = make_float2(0.f, 0.f);

    for (int c0 = s; c0 < e; c0 += 32) {
        int idx = c0 + lane;
        long long ed = 0;
        if (idx < e) ed = g_pedge[idx];
        int cnt = min(32, e - c0);          // multiple of 4 (rows padded)
        for (int i = 0; i < cnt; i += 4) {
            long long p0 = __shfl_sync(0xffffffffu, ed, i);
            long long p1 = __shfl_sync(0xffffffffu, ed, i + 1);
            long long p2 = __shfl_sync(0xffffffffu, ed, i + 2);
            long long p3 = __shfl_sync(0xffffffffu, ed, i + 3);
            int   cc0 = (int)p0;  float v0 = __int_as_float((int)(p0 >> 32));
            int   cc1 = (int)p1;  float v1 = __int_as_float((int)(p1 >> 32));
            int   cc2 = (int)p2;  float v2 = __int_as_float((int)(p2 >> 32));
            int   cc3 = (int)p3;  float v3 = __int_as_float((int)(p3 >> 32));
            float2 x0 = __half22float2(g_embH[(size_t)cc0 * 32 + lane]);
            float2 x1 = __half22float2(g_embH[(size_t)cc1 * 32 + lane]);
            float2 x2 = __half22float2(g_embH[(size_t)cc2 * 32 + lane]);
            float2 x3 = __half22float2(g_embH[(size_t)cc3 * 32 + lane]);
            a0.x = fmaf(v0, x0.x, a0.x); a0.y = fmaf(v0, x0.y, a0.y);
            a1.x = fmaf(v1, x1.x, a1.x); a1.y = fmaf(v1, x1.y, a1.y);
            a2.x = fmaf(v2, x2.x, a2.x); a2.y = fmaf(v2, x2.y, a2.y);
            a3.x = fmaf(v3, x3.x, a3.x); a3.y = fmaf(v3, x3.y, a3.y);
        }
    }
    a0.x += a1.x + a2.x + a3.x;
    a0.y += a1.y + a2.y + a3.y;
    reinterpret_cast<float2*>(g_agg)[(size_t)w * 32 + lane] = a0;
}

// ---------------- fused dense layer (tf32 MMA, 2 blocks/SM) ----------------
//   sx = (agg+emb) @ W1^T + b1
//   ox = agg * (emb @ W2^T + b2)
//   out = leaky_relu(sx + ox, 0.01)
// Dual-writes fp32 dst + fp16 mirror for the next layer's spmm gather.
#define BM 64
#define WS2 70
#define NF2 (BM * WS2)
#define F_B1 (3 * NF2 * 2)
#define F_B2 (F_B1 + DD)
#define DSM_FLOATS (F_B2 + DD)                  // 27008 floats = 108032 B

__global__ void __launch_bounds__(256, 2) dense_kernel(
        const float* __restrict__ src,
        const float* __restrict__ w1,
        const float* __restrict__ b1,
        const float* __restrict__ w2,
        const float* __restrict__ b2,
        float* __restrict__ dst) {
    extern __shared__ float sm[];
    float2* sXA = reinterpret_cast<float2*>(sm);
    float2* sW1 = sXA + NF2;
    float2* sW2 = sW1 + NF2;
    float* sB1 = sm + F_B1;
    float* sB2 = sm + F_B2;

    const int tid = threadIdx.x;
    const int base = blockIdx.x * BM;
    const int nrows = min(BM, NN - base);

    for (int idx = tid; idx < DD * DD; idx += 256) {
        int j = idx >> 6, k = idx & 63;
        unsigned h, l;
        tfsplit(w1[idx], h, l);
        sW1[j * WS2 + k] = make_float2(__uint_as_float(h), __uint_as_float(l));
        tfsplit(w2[idx], h, l);
        sW2[j * WS2 + k] = make_float2(__uint_as_float(h), __uint_as_float(l));
    }
    if (tid < DD) { sB1[tid] = b1[tid]; sB2[tid] = b2[tid]; }

    {
        const float4* srcv = reinterpret_cast<const float4*>(src);
        const float4* aggv = reinterpret_cast<const float4*>(g_agg);
        for (int idx = tid; idx < BM * ROW4; idx += 256) {
            int n = idx >> 4, c = idx & 15;
            float4 xv = make_float4(0.f, 0.f, 0.f, 0.f);
            float4 av = xv;
            if (n < nrows) {
                xv = srcv[(size_t)(base + n) * ROW4 + c];
                av = aggv[(size_t)(base + n) * ROW4 + c];
            }
            float2* p = sXA + n * WS2 + 4 * c;
            p[0] = make_float2(xv.x, xv.x + av.x);
            p[1] = make_float2(xv.y, xv.y + av.y);
            p[2] = make_float2(xv.z, xv.z + av.z);
            p[3] = make_float2(xv.w, xv.w + av.w);
        }
    }
    __syncthreads();

    const int wid  = tid >> 5;
    const int lane = tid & 31;
    const int g  = lane >> 2;
    const int tg = lane & 3;
    const int wr = wid & 3;
    const int wj = wid >> 2;
    const int n0 = wr * 16;

    float acc1[4][4], acc2[4][4];
#pragma unroll
    for (int jt = 0; jt < 4; jt++)
#pragma unroll
        for (int p = 0; p < 4; p++) { acc1[jt][p] = 0.f; acc2[jt][p] = 0.f; }

#pragma unroll 2
    for (int ks = 0; ks < 8; ks++) {
        const int k0 = ks * 8;
        unsigned xh[4], xl[4], axh[4], axl[4];
        {
            float2 q0 = sXA[(n0 + g)     * WS2 + k0 + tg];
            float2 q1 = sXA[(n0 + g + 8) * WS2 + k0 + tg];
            float2 q2 = sXA[(n0 + g)     * WS2 + k0 + tg + 4];
            float2 q3 = sXA[(n0 + g + 8) * WS2 + k0 + tg + 4];
            tfsplit(q0.x, xh[0], xl[0]); tfsplit(q0.y, axh[0], axl[0]);
            tfsplit(q1.x, xh[1], xl[1]); tfsplit(q1.y, axh[1], axl[1]);
            tfsplit(q2.x, xh[2], xl[2]); tfsplit(q2.y, axh[2], axl[2]);
            tfsplit(q3.x, xh[3], xl[3]); tfsplit(q3.y, axh[3], axl[3]);
        }
#pragma unroll
        for (int jt = 0; jt < 4; jt++) {
            const int jb = wj * 32 + jt * 8 + g;
            float2 p10 = sW1[jb * WS2 + k0 + tg];
            float2 p11 = sW1[jb * WS2 + k0 + tg + 4];
            float2 p20 = sW2[jb * WS2 + k0 + tg];
            float2 p21 = sW2[jb * WS2 + k0 + tg + 4];
            unsigned w1h0 = __float_as_uint(p10.x), w1l0 = __float_as_uint(p10.y);
            unsigned w1h1 = __float_as_uint(p11.x), w1l1 = __float_as_uint(p11.y);
            unsigned w2h0 = __float_as_uint(p20.x), w2l0 = __float_as_uint(p20.y);
            unsigned w2h1 = __float_as_uint(p21.x), w2l1 = __float_as_uint(p21.y);
            mma_tf32(acc1[jt], axh, w1h0, w1h1);
            mma_tf32(acc1[jt], axh, w1l0, w1l1);
            mma_tf32(acc1[jt], axl, w1h0, w1h1);
            mma_tf32(acc2[jt], xh,  w2h0, w2h1);
            mma_tf32(acc2[jt], xh,  w2l0, w2l1);
            mma_tf32(acc2[jt], xl,  w2h0, w2h1);
        }
    }

    const int row0 = n0 + g;
    const int row1 = row0 + 8;
#pragma unroll
    for (int jt = 0; jt < 4; jt++) {
        const int j = wj * 32 + jt * 8 + tg * 2;
        float bj0 = sB1[j], bj1 = sB1[j + 1];
        float cj0 = sB2[j], cj1 = sB2[j + 1];
        if (row0 < nrows) {
            float2 qa = sXA[row0 * WS2 + j];
            float2 qb = sXA[row0 * WS2 + j + 1];
            float ag0 = qa.y - qa.x;
            float ag1 = qb.y - qb.x;
            float v0 = (acc1[jt][0] + bj0) + ag0 * (acc2[jt][0] + cj0);
            float v1 = (acc1[jt][1] + bj1) + ag1 * (acc2[jt][1] + cj1);
            v0 = v0 > 0.f ? v0 : 0.01f * v0;
            v1 = v1 > 0.f ? v1 : 0.01f * v1;
            size_t o = (size_t)(base + row0) * DD + j;
            *reinterpret_cast<float2*>(dst + o) = make_float2(v0, v1);
            g_embH[o >> 1] = __floats2half2_rn(v0, v1);
        }
        if (row1 < nrows) {
            float2 qa = sXA[row1 * WS2 + j];
            float2 qb = sXA[row1 * WS2 + j + 1];
            float ag0 = qa.y - qa.x;
            float ag1 = qb.y - qb.x;
            float v0 = (acc1[jt][2] + bj0) + ag0 * (acc2[jt][2] + cj0);
            float v1 = (acc1[jt][3] + bj1) + ag1 * (acc2[jt][3] + cj1);
            v0 = v0 > 0.f ? v0 : 0.01f * v0;
            v1 = v1 > 0.f ? v1 : 0.01f * v1;
            size_t o = (size_t)(base + row1) * DD + j;
            *reinterpret_cast<float2*>(dst + o) = make_float2(v0, v1);
            g_embH[o >> 1] = __floats2half2_rn(v0, v1);
        }
    }
}

// ---------------- gather + loss ----------------

__global__ void gather_kernel(const float* __restrict__ emb,
                              const int* __restrict__ user,
                              const int* __restrict__ pos,
                              const int* __restrict__ neg,
                              int layer) {
    unsigned t = blockIdx.x * blockDim.x + threadIdx.x;
    if (t >= BB * 16) return;
    unsigned i = t >> 4;
    unsigned c = t & 15u;
    unsigned doff = i * 64 + (unsigned)layer * 16 + c;
    const float4* ev = reinterpret_cast<const float4*>(emb);
    reinterpret_cast<float4*>(g_ue)[doff] = ev[(size_t)user[i] * ROW4 + c];
    reinterpret_cast<float4*>(g_pe)[doff] = ev[(size_t)pos [i] * ROW4 + c];
    reinterpret_cast<float4*>(g_ne)[doff] = ev[(size_t)neg [i] * ROW4 + c];
}

__global__ void zero_out_kernel(float* out) {
    if (threadIdx.x == 0 && blockIdx.x == 0) out[0] = 0.f;
}

__global__ void loss_kernel(float* __restrict__ out) {
    int i = blockIdx.x * blockDim.x + threadIdx.x;
    float dp = 0.f, dn = 0.f;
    if (i < BB) {
        const float4* uv = reinterpret_cast<const float4*>(g_ue);
        const float4* pv = reinterpret_cast<const float4*>(g_pe);
        const float4* nv = reinterpret_cast<const float4*>(g_ne);
#pragma unroll 8
        for (int c = 0; c < 64; c++) {
            float4 u = uv[(size_t)i * 64 + c];
            float4 p = pv[(size_t)i * 64 + c];
            float4 q = nv[(size_t)i * 64 + c];
            dp += u.x*p.x + u.y*p.y + u.z*p.z + u.w*p.w;
            dn += u.x*q.x + u.y*q.y + u.z*q.z + u.w*q.w;
        }
    }
    float d = dp - dn;
    float l = (i < BB) ? (fmaxf(-d, 0.f) + log1pf(expf(-fabsf(d)))) : 0.f;

    __shared__ float red[256];
    red[threadIdx.x] = l;
    __syncthreads();
    for (int s = 128; s > 0; s >>= 1) {
        if (threadIdx.x < s) red[threadIdx.x] += red[threadIdx.x + s];
        __syncthreads();
    }
    if (threadIdx.x == 0) atomicAdd(out, red[0]);
}

// ---------------- launch ----------------

extern "C" void kernel_launch(void* const* d_in, const int* in_sizes, int n_in,
                              void* d_out, int out_size) {
    const float* emb  = (const float*)d_in[0];
    const float* w1w  = (const float*)d_in[1];
    const float* w1b  = (const float*)d_in[2];
    const float* w2w  = (const float*)d_in[3];
    const float* w2b  = (const float*)d_in[4];
    const float* vals = (const float*)d_in[5];
    const int*   rows = (const int*)d_in[6];
    const int*   cols = (const int*)d_in[7];
    const int*   user = (const int*)d_in[8];
    const int*   pos  = (const int*)d_in[9];
    const int*   neg  = (const int*)d_in[10];
    float* out = (float*)d_out;

    void *pA = nullptr, *pB = nullptr;
    cudaGetSymbolAddress(&pA, g_embA);
    cudaGetSymbolAddress(&pB, g_embB);
    float* eA = (float*)pA;
    float* eB = (float*)pB;

    const int SMEM_BYTES = DSM_FLOATS * 4;   // 108032
    cudaFuncSetAttribute(dense_kernel,
                         cudaFuncAttributeMaxDynamicSharedMemorySize, SMEM_BYTES);

    const int EB = (EE + 255) / 256;
    const int NB = (NN + 255) / 256;
    const int CB = (NN * DD / 2 + 255) / 256;
    const int SPB = (NN + 7) / 8;
    const int DB = (NN + BM - 1) / BM;        // 782
    const int GB = (BB * 16 + 255) / 256;

    // ---- CSR build (per launch; deterministic workload) ----
    zero_cnt_kernel<<<NB, 256>>>();
    hist_kernel<<<EB, 256>>>(rows);
    scan_kernel<<<1, SCAN_T>>>();
    pad_zero_kernel<<<NB, 256>>>();
    scatter_kernel<<<EB, 256>>>(rows, cols, vals);

    // fp16 mirror of initial embedding + layer-0 gather
    conv_half_kernel<<<CB, 256>>>(emb);
    gather_kernel<<<GB, 256>>>(emb, user, pos, neg, 0);

    // layer 1: emb -> eA (dense dual-writes fp16 mirror of eA)
    spmm_csr_kernel<<<SPB, 256>>>();
    dense_kernel<<<DB, 256, SMEM_BYTES>>>(emb, w1w, w1b, w2w, w2b, eA);
    gather_kernel<<<GB, 256>>>(eA, user, pos, neg, 1);

    // layer 2: eA -> eB
    spmm_csr_kernel<<<SPB, 256>>>();
    dense_kernel<<<DB, 256, SMEM_BYTES>>>(eA, w1w + 4096, w1b + 64, w2w + 4096, w2b + 64, eB);
    gather_kernel<<<GB, 256>>>(eB, user, pos, neg, 2);

    // layer 3: eB -> eA
    spmm_csr_kernel<<<SPB, 256>>>();
    dense_kernel<<<DB, 256, SMEM_BYTES>>>(eB, w1w + 8192, w1b + 128, w2w + 8192, w2b + 128, eA);
    gather_kernel<<<GB, 256>>>(eA, user, pos, neg, 3);

    // loss
    zero_out_kernel<<<1, 32>>>(out);
    loss_kernel<<<BB / 256, 256>>>(out);
}

// round 16
// speedup vs baseline: 1.1911x; 1.1911x over previous
#include <cuda_runtime.h>
#include <cuda_fp16.h>
#include <math.h>

#define NN 50000
#define DD 64
#define EE 1250000
#define BB 4096
#define ROW4 16              // float4 per embedding row

// ---------------- scratch (device globals; no allocation) ----------------
__device__ float g_embA[NN * DD];
__device__ float g_embB[NN * DD];
__device__ float g_agg [NN * DD];
__device__ float g_ue[BB * 256];
__device__ float g_pe[BB * 256];
__device__ float g_ne[BB * 256];

// ---------------- fp16 mma helper ----------------
__device__ __forceinline__ void mma_f16(float* d, const unsigned* a,
                                        unsigned b0, unsigned b1) {
    asm volatile(
        "mma.sync.aligned.m16n8k16.row.col.f32.f16.f16.f32 "
        "{%0,%1,%2,%3},{%4,%5,%6,%7},{%8,%9},{%0,%1,%2,%3};"
        : "+f"(d[0]), "+f"(d[1]), "+f"(d[2]), "+f"(d[3])
        : "r"(a[0]), "r"(a[1]), "r"(a[2]), "r"(a[3]), "r"(b0), "r"(b1));
}
__device__ __forceinline__ void hsplit(float f, __half& hi, __half& lo) {
    hi = __float2half_rn(f);
    lo = __float2half_rn(f - __half2float(hi));
}

// ---------------- kernels ----------------

__global__ void zero_agg_kernel() {
    int i = blockIdx.x * blockDim.x + threadIdx.x;
    if (i < NN * DD / 4)
        reinterpret_cast<float4*>(g_agg)[i] = make_float4(0.f, 0.f, 0.f, 0.f);
}

// 16 threads per edge; one float4 chunk per thread; vector red scatter.
__global__ void spmm_kernel(const float* __restrict__ emb,
                            const float* __restrict__ vals,
                            const int*  __restrict__ rows,
                            const int*  __restrict__ cols) {
    unsigned gid = blockIdx.x * blockDim.x + threadIdx.x;
    unsigned e = gid >> 4;
    unsigned c = gid & 15u;
    if (e >= EE) return;
    int col = cols[e];
    int row = rows[e];
    float v = vals[e];
    float4 x = reinterpret_cast<const float4*>(emb)[(size_t)col * ROW4 + c];
    float4* dst = reinterpret_cast<float4*>(g_agg) + (size_t)row * ROW4 + c;
    asm volatile("red.global.add.v4.f32 [%0], {%1,%2,%3,%4};"
                 :: "l"(dst), "f"(v * x.x), "f"(v * x.y), "f"(v * x.z), "f"(v * x.w)
                 : "memory");
}

// ---------------- fused dense layer (fp16 3-product MMA, 3 blocks/SM) ----------------
//   sx = (agg+emb) @ W1^T + b1
//   ox = agg * (emb @ W2^T + b2)
//   out = leaky_relu(sx + ox, 0.01)
// Block = 64 nodes x 64 outputs, 256 threads (8 warps). Warp = 16 rows x 32 j.
// smem: 8 pre-split half planes (xh,xl,axh,axl,w1h,w1l,w2h,w2l), stride 72.
// m16n8k16 f16 MMA, fp32 accum; 3 products (h*h + h*l + l*h) ~ 2^-22 residual.
#define BM 64
#define HS 72                                   // halves per row per plane
#define PL (BM * HS)                            // 4608 halves per plane
#define F_B1 (8 * PL / 2)                       // float index after 8 planes = 18432
#define F_B2 (F_B1 + DD)
#define DSM_BYTES (8 * PL * 2 + 2 * DD * 4)     // 73728 + 512 = 74240

__global__ void __launch_bounds__(256, 3) dense_kernel(
        const float* __restrict__ src,
        const float* __restrict__ w1,
        const float* __restrict__ b1,
        const float* __restrict__ w2,
        const float* __restrict__ b2,
        float* __restrict__ dst) {
    extern __shared__ __half smh[];
    __half* sXh  = smh;
    __half* sXl  = smh + PL;
    __half* sAXh = smh + 2 * PL;
    __half* sAXl = smh + 3 * PL;
    __half* sW1h = smh + 4 * PL;
    __half* sW1l = smh + 5 * PL;
    __half* sW2h = smh + 6 * PL;
    __half* sW2l = smh + 7 * PL;
    float* sB1 = reinterpret_cast<float*>(smh) + F_B1;
    float* sB2 = reinterpret_cast<float*>(smh) + F_B2;

    const int tid = threadIdx.x;
    const int base = blockIdx.x * BM;
    const int nrows = min(BM, NN - base);

    // ---- stage W planes: sW*[j][k] ----
    for (int idx = tid; idx < DD * DD; idx += 256) {
        int j = idx >> 6, k = idx & 63;
        __half h, l;
        hsplit(w1[idx], h, l);
        sW1h[j * HS + k] = h; sW1l[j * HS + k] = l;
        hsplit(w2[idx], h, l);
        sW2h[j * HS + k] = h; sW2l[j * HS + k] = l;
    }
    if (tid < DD) { sB1[tid] = b1[tid]; sB2[tid] = b2[tid]; }

    // ---- stage X planes: x and ax = x+agg (zero-pad tail rows) ----
    {
        const float4* srcv = reinterpret_cast<const float4*>(src);
        const float4* aggv = reinterpret_cast<const float4*>(g_agg);
        for (int idx = tid; idx < BM * ROW4; idx += 256) {
            int n = idx >> 4, c = idx & 15;
            float4 xv = make_float4(0.f, 0.f, 0.f, 0.f);
            float4 av = xv;
            if (n < nrows) {
                xv = srcv[(size_t)(base + n) * ROW4 + c];
                av = aggv[(size_t)(base + n) * ROW4 + c];
            }
            float xs[4] = { xv.x, xv.y, xv.z, xv.w };
            float as[4] = { xv.x + av.x, xv.y + av.y, xv.z + av.z, xv.w + av.w };
#pragma unroll
            for (int i = 0; i < 4; i++) {
                int k = 4 * c + i;
                __half h, l;
                hsplit(xs[i], h, l);
                sXh [n * HS + k] = h; sXl [n * HS + k] = l;
                hsplit(as[i], h, l);
                sAXh[n * HS + k] = h; sAXl[n * HS + k] = l;
            }
        }
    }
    __syncthreads();

    const int wid  = tid >> 5;
    const int lane = tid & 31;
    const int g  = lane >> 2;      // 0..7
    const int tg = lane & 3;       // 0..3
    const int wr = wid & 3;        // row group: rows wr*16 .. wr*16+15
    const int wj = wid >> 2;       // j half: j wj*32 .. wj*32+31
    const int n0 = wr * 16;
    const int r0 = n0 + g;
    const int r1 = r0 + 8;

    float acc1[4][4], acc2[4][4];
#pragma unroll
    for (int jt = 0; jt < 4; jt++)
#pragma unroll
        for (int p = 0; p < 4; p++) { acc1[jt][p] = 0.f; acc2[jt][p] = 0.f; }

#pragma unroll
    for (int ks = 0; ks < 4; ks++) {
        const int kb = ks * 16 + 2 * tg;
        const int o00 = r0 * HS + kb, o10 = r1 * HS + kb;
        unsigned xhf[4], xlf[4], ahf[4], alf[4];
        xhf[0] = *reinterpret_cast<const unsigned*>(sXh + o00);
        xhf[1] = *reinterpret_cast<const unsigned*>(sXh + o10);
        xhf[2] = *reinterpret_cast<const unsigned*>(sXh + o00 + 8);
        xhf[3] = *reinterpret_cast<const unsigned*>(sXh + o10 + 8);
        xlf[0] = *reinterpret_cast<const unsigned*>(sXl + o00);
        xlf[1] = *reinterpret_cast<const unsigned*>(sXl + o10);
        xlf[2] = *reinterpret_cast<const unsigned*>(sXl + o00 + 8);
        xlf[3] = *reinterpret_cast<const unsigned*>(sXl + o10 + 8);
        ahf[0] = *reinterpret_cast<const unsigned*>(sAXh + o00);
        ahf[1] = *reinterpret_cast<const unsigned*>(sAXh + o10);
        ahf[2] = *reinterpret_cast<const unsigned*>(sAXh + o00 + 8);
        ahf[3] = *reinterpret_cast<const unsigned*>(sAXh + o10 + 8);
        alf[0] = *reinterpret_cast<const unsigned*>(sAXl + o00);
        alf[1] = *reinterpret_cast<const unsigned*>(sAXl + o10);
        alf[2] = *reinterpret_cast<const unsigned*>(sAXl + o00 + 8);
        alf[3] = *reinterpret_cast<const unsigned*>(sAXl + o10 + 8);
#pragma unroll
        for (int jt = 0; jt < 4; jt++) {
            const int wo = (wj * 32 + jt * 8 + g) * HS + kb;
            unsigned w1h0 = *reinterpret_cast<const unsigned*>(sW1h + wo);
            unsigned w1h1 = *reinterpret_cast<const unsigned*>(sW1h + wo + 8);
            unsigned w1l0 = *reinterpret_cast<const unsigned*>(sW1l + wo);
            unsigned w1l1 = *reinterpret_cast<const unsigned*>(sW1l + wo + 8);
            unsigned w2h0 = *reinterpret_cast<const unsigned*>(sW2h + wo);
            unsigned w2h1 = *reinterpret_cast<const unsigned*>(sW2h + wo + 8);
            unsigned w2l0 = *reinterpret_cast<const unsigned*>(sW2l + wo);
            unsigned w2l1 = *reinterpret_cast<const unsigned*>(sW2l + wo + 8);
            mma_f16(acc1[jt], ahf, w1h0, w1h1);
            mma_f16(acc1[jt], ahf, w1l0, w1l1);
            mma_f16(acc1[jt], alf, w1h0, w1h1);
            mma_f16(acc2[jt], xhf, w2h0, w2h1);
            mma_f16(acc2[jt], xhf, w2l0, w2l1);
            mma_f16(acc2[jt], xlf, w2h0, w2h1);
        }
    }

    // ---- epilogue: agg = (axh+axl)-(xh+xl), bias, elementwise, leaky, store ----
#pragma unroll
    for (int jt = 0; jt < 4; jt++) {
        const int j = wj * 32 + jt * 8 + tg * 2;
        float bj0 = sB1[j], bj1 = sB1[j + 1];
        float cj0 = sB2[j], cj1 = sB2[j + 1];
        if (r0 < nrows) {
            float2 fxh = __half22float2(*reinterpret_cast<__half2*>(sXh  + r0 * HS + j));
            float2 fxl = __half22float2(*reinterpret_cast<__half2*>(sXl  + r0 * HS + j));
            float2 fah = __half22float2(*reinterpret_cast<__half2*>(sAXh + r0 * HS + j));
            float2 fal = __half22float2(*reinterpret_cast<__half2*>(sAXl + r0 * HS + j));
            float ag0 = (fah.x + fal.x) - (fxh.x + fxl.x);
            float ag1 = (fah.y + fal.y) - (fxh.y + fxl.y);
            float v0 = (acc1[jt][0] + bj0) + ag0 * (acc2[jt][0] + cj0);
            float v1 = (acc1[jt][1] + bj1) + ag1 * (acc2[jt][1] + cj1);
            v0 = v0 > 0.f ? v0 : 0.01f * v0;
            v1 = v1 > 0.f ? v1 : 0.01f * v1;
            *reinterpret_cast<float2*>(dst + (size_t)(base + r0) * DD + j) =
                make_float2(v0, v1);
        }
        if (r1 < nrows) {
            float2 fxh = __half22float2(*reinterpret_cast<__half2*>(sXh  + r1 * HS + j));
            float2 fxl = __half22float2(*reinterpret_cast<__half2*>(sXl  + r1 * HS + j));
            float2 fah = __half22float2(*reinterpret_cast<__half2*>(sAXh + r1 * HS + j));
            float2 fal = __half22float2(*reinterpret_cast<__half2*>(sAXl + r1 * HS + j));
            float ag0 = (fah.x + fal.x) - (fxh.x + fxl.x);
            float ag1 = (fah.y + fal.y) - (fxh.y + fxl.y);
            float v0 = (acc1[jt][2] + bj0) + ag0 * (acc2[jt][2] + cj0);
            float v1 = (acc1[jt][3] + bj1) + ag1 * (acc2[jt][3] + cj1);
            v0 = v0 > 0.f ? v0 : 0.01f * v0;
            v1 = v1 > 0.f ? v1 : 0.01f * v1;
            *reinterpret_cast<float2*>(dst + (size_t)(base + r1) * DD + j) =
                make_float2(v0, v1);
        }
    }
}

// ---------------- gather + loss ----------------

__global__ void gather_kernel(const float* __restrict__ emb,
                              const int* __restrict__ user,
                              const int* __restrict__ pos,
                              const int* __restrict__ neg,
                              int layer) {
    unsigned t = blockIdx.x * blockDim.x + threadIdx.x;
    if (t >= BB * 16) return;
    unsigned i = t >> 4;
    unsigned c = t & 15u;
    unsigned doff = i * 64 + (unsigned)layer * 16 + c;
    const float4* ev = reinterpret_cast<const float4*>(emb);
    reinterpret_cast<float4*>(g_ue)[doff] = ev[(size_t)user[i] * ROW4 + c];
    reinterpret_cast<float4*>(g_pe)[doff] = ev[(size_t)pos [i] * ROW4 + c];
    reinterpret_cast<float4*>(g_ne)[doff] = ev[(size_t)neg [i] * ROW4 + c];
}

__global__ void zero_out_kernel(float* out) {
    if (threadIdx.x == 0 && blockIdx.x == 0) out[0] = 0.f;
}

__global__ void loss_kernel(float* __restrict__ out) {
    int i = blockIdx.x * blockDim.x + threadIdx.x;
    float dp = 0.f, dn = 0.f;
    if (i < BB) {
        const float4* uv = reinterpret_cast<const float4*>(g_ue);
        const float4* pv = reinterpret_cast<const float4*>(g_pe);
        const float4* nv = reinterpret_cast<const float4*>(g_ne);
#pragma unroll 8
        for (int c = 0; c < 64; c++) {
            float4 u = uv[(size_t)i * 64 + c];
            float4 p = pv[(size_t)i * 64 + c];
            float4 q = nv[(size_t)i * 64 + c];
            dp += u.x*p.x + u.y*p.y + u.z*p.z + u.w*p.w;
            dn += u.x*q.x + u.y*q.y + u.z*q.z + u.w*q.w;
        }
    }
    float d = dp - dn;
    float l = (i < BB) ? (fmaxf(-d, 0.f) + log1pf(expf(-fabsf(d)))) : 0.f;

    __shared__ float red[256];
    red[threadIdx.x] = l;
    __syncthreads();
    for (int s = 128; s > 0; s >>= 1) {
        if (threadIdx.x < s) red[threadIdx.x] += red[threadIdx.x + s];
        __syncthreads();
    }
    if (threadIdx.x == 0) atomicAdd(out, red[0]);
}

// ---------------- launch ----------------

extern "C" void kernel_launch(void* const* d_in, const int* in_sizes, int n_in,
                              void* d_out, int out_size) {
    const float* emb  = (const float*)d_in[0];
    const float* w1w  = (const float*)d_in[1];
    const float* w1b  = (const float*)d_in[2];
    const float* w2w  = (const float*)d_in[3];
    const float* w2b  = (const float*)d_in[4];
    const float* vals = (const float*)d_in[5];
    const int*   rows = (const int*)d_in[6];
    const int*   cols = (const int*)d_in[7];
    const int*   user = (const int*)d_in[8];
    const int*   pos  = (const int*)d_in[9];
    const int*   neg  = (const int*)d_in[10];
    float* out = (float*)d_out;

    void *pA = nullptr, *pB = nullptr;
    cudaGetSymbolAddress(&pA, g_embA);
    cudaGetSymbolAddress(&pB, g_embB);
    float* eA = (float*)pA;
    float* eB = (float*)pB;

    cudaFuncSetAttribute(dense_kernel,
                         cudaFuncAttributeMaxDynamicSharedMemorySize, DSM_BYTES);

    const int ZB = (NN * DD / 4 + 255) / 256;
    const int SB = (EE * 16) / 256;           // 78125 exact
    const int DB = (NN + BM - 1) / BM;        // 782
    const int GB = (BB * 16 + 255) / 256;

    // layer 0 input gather
    gather_kernel<<<GB, 256>>>(emb, user, pos, neg, 0);

    // layer 1: emb -> eA
    zero_agg_kernel<<<ZB, 256>>>();
    spmm_kernel<<<SB, 256>>>(emb, vals, rows, cols);
    dense_kernel<<<DB, 256, DSM_BYTES>>>(emb, w1w, w1b, w2w, w2b, eA);
    gather_kernel<<<GB, 256>>>(eA, user, pos, neg, 1);

    // layer 2: eA -> eB
    zero_agg_kernel<<<ZB, 256>>>();
    spmm_kernel<<<SB, 256>>>(eA, vals, rows, cols);
    dense_kernel<<<DB, 256, DSM_BYTES>>>(eA, w1w + 4096, w1b + 64, w2w + 4096, w2b + 64, eB);
    gather_kernel<<<GB, 256>>>(eB, user, pos, neg, 2);

    // layer 3: eB -> eA
    zero_agg_kernel<<<ZB, 256>>>();
    spmm_kernel<<<SB, 256>>>(eB, vals, rows, cols);
    dense_kernel<<<DB, 256, DSM_BYTES>>>(eB, w1w + 8192, w1b + 128, w2w + 8192, w2b + 128, eA);
    gather_kernel<<<GB, 256>>>(eA, user, pos, neg, 3);

    // loss
    zero_out_kernel<<<1, 32>>>(out);
    loss_kernel<<<BB / 256, 256>>>(out);
}